// round 13
// baseline (speedup 1.0000x reference)
#include <cuda_runtime.h>
#include <cuda_fp16.h>
#include <cstdint>

#define VOCAB   32000
#define EMB_DIM 2048
#define N_COMP  64
#define SEQ_L   128
#define BATCH   4096
#define SPLIT   8

// ---------------------------------------------------------------------------
// Static scratch (no allocation)
// ---------------------------------------------------------------------------
__device__ float  g_part[SPLIT][N_COMP * EMB_DIM];   // pool partials (4 MB)
__device__ __half g_BT[EMB_DIM * N_COMP];            // pooled^T fp16 [n][k]
__device__ __half g_A[BATCH * N_COMP];               // ratio fp16 [b][k]

// ---------------------------------------------------------------------------
// Kernel 1: pooled partial sums (proven R5 form). grid=(N_COMP,4,SPLIT), 128 thr.
// ---------------------------------------------------------------------------
__global__ void pool_kernel(const int* __restrict__ ids,
                            const float* __restrict__ emb) {
    __shared__ int s_ids[SEQ_L / SPLIT];
    const int comp = blockIdx.x;
    const int z = blockIdx.z;
    const int t = threadIdx.x;
    const int TOK = SEQ_L / SPLIT;              // 16
    if (t < TOK) s_ids[t] = ids[comp * SEQ_L + z * TOK + t];
    __syncthreads();

    const int col4 = blockIdx.y * 128 + t;      // 0..511
    const float4* __restrict__ emb4 = (const float4*)emb;

    float4 acc = make_float4(0.f, 0.f, 0.f, 0.f);
#pragma unroll
    for (int l = 0; l < TOK; l++) {
        const int row = s_ids[l];
        float4 v = __ldg(&emb4[(size_t)row * (EMB_DIM / 4) + col4]);
        acc.x += v.x; acc.y += v.y; acc.z += v.z; acc.w += v.w;
    }
    ((float4*)g_part[z])[comp * (EMB_DIM / 4) + col4] = acc;
}

// ---------------------------------------------------------------------------
// fp16 helpers
// ---------------------------------------------------------------------------
__device__ __forceinline__ uint32_t pack_h2(__half a, __half b) {
    __half2 h = __halves2half2(a, b);
    return *reinterpret_cast<uint32_t*>(&h);
}

// ---------------------------------------------------------------------------
// Kernel 2: converts. blocks 0..63: pooled reduce+scale+round+transpose.
//           blocks 64..191: ratio fp32 -> fp16 (coalesced).
// ---------------------------------------------------------------------------
__global__ void cvt_kernel(const float* __restrict__ ratio) {
    const int bx = blockIdx.x;
    if (bx < 64) {
        const int lane = threadIdx.x & 31;
        const int ty = threadIdx.x >> 5;            // 0..3
        const int n = bx * 32 + lane;               // 0..2047
        const int k0 = ty * 16;

        uint32_t h2[8];
#pragma unroll
        for (int kp = 0; kp < 8; kp++) {
            float sa = 0.f, sb = 0.f;
#pragma unroll
            for (int z = 0; z < SPLIT; z++) {
                sa += g_part[z][(k0 + 2 * kp) * EMB_DIM + n];
                sb += g_part[z][(k0 + 2 * kp + 1) * EMB_DIM + n];
            }
            h2[kp] = pack_h2(__float2half_rn(sa * (1.0f / SEQ_L)),
                             __float2half_rn(sb * (1.0f / SEQ_L)));
        }
        uint4* dh = (uint4*)g_BT;      // row n = 8 uint4 (64 fp16)
#pragma unroll
        for (int c = 0; c < 2; c++) {
            dh[n * 8 + ty * 2 + c] = make_uint4(h2[4*c], h2[4*c+1], h2[4*c+2], h2[4*c+3]);
        }
    } else {
        const int base = (bx - 64) * 512;           // float4 index base
        const float4* __restrict__ rg = (const float4*)ratio;
        uint2* __restrict__ dst = (uint2*)g_A;
#pragma unroll
        for (int j = 0; j < 4; j++) {
            const int gid = base + j * 128 + threadIdx.x;  // 0..65535
            float4 v = __ldg(&rg[gid]);
            dst[gid] = make_uint2(pack_h2(__float2half_rn(v.x), __float2half_rn(v.y)),
                                  pack_h2(__float2half_rn(v.z), __float2half_rn(v.w)));
        }
    }
}

// ---------------------------------------------------------------------------
// Kernel 3: HMMA mix, single fp16 product, cp.async staging (R12, unchanged).
// CTA: 128 b-rows x 128 d-cols, 256 threads (4 warps m x 2 warps n).
// ---------------------------------------------------------------------------
#define MMA16816(c, a, b0, b1) \
    asm volatile("mma.sync.aligned.m16n8k16.row.col.f32.f16.f16.f32 " \
        "{%0,%1,%2,%3}, {%4,%5,%6,%7}, {%8,%9}, {%0,%1,%2,%3};" \
        : "+f"((c)[0]), "+f"((c)[1]), "+f"((c)[2]), "+f"((c)[3]) \
        : "r"((a)[0]), "r"((a)[1]), "r"((a)[2]), "r"((a)[3]), "r"(b0), "r"(b1))

#define LDSM_X4(r0, r1, r2, r3, addr) \
    asm volatile("ldmatrix.sync.aligned.m8n8.x4.shared.b16 {%0,%1,%2,%3}, [%4];" \
        : "=r"(r0), "=r"(r1), "=r"(r2), "=r"(r3) : "r"(addr))

#define CP_ASYNC16(dst, src) \
    asm volatile("cp.async.ca.shared.global [%0], [%1], 16;" :: "r"(dst), "l"(src))
#define CP_COMMIT() asm volatile("cp.async.commit_group;" ::: "memory")
#define CP_WAIT0()  asm volatile("cp.async.wait_group 0;" ::: "memory")

#define ROWB 144            // padded row pitch in bytes (72 halves)
#define OFF_A  0
#define OFF_B  (128 * ROWB)
#define MIX_SMEM (2 * 128 * ROWB)   // 36864 B

__device__ __forceinline__ uint32_t smem_u32(const void* p) {
    uint32_t a;
    asm("{ .reg .u64 t; cvta.to.shared.u64 t, %1; cvt.u32.u64 %0, t; }" : "=r"(a) : "l"(p));
    return a;
}

__global__ void __launch_bounds__(256)
mix_kernel(float* __restrict__ out) {
    extern __shared__ char smem[];
    const uint32_t sb = smem_u32(smem);

    const int tid = threadIdx.x;
    const int wid = tid >> 5;
    const int lane = tid & 31;
    const int g = lane >> 2;          // 0..7
    const int t = lane & 3;           // 0..3
    const int dBase = blockIdx.x * 128;
    const int bBase = blockIdx.y * 128;

    // --- stage A + B via cp.async: both are 128 rows x 8 int4 (128 B) ---
    {
        const int4* __restrict__ ag = (const int4*)g_A;
        const int4* __restrict__ bg = (const int4*)g_BT;
#pragma unroll
        for (int i = 0; i < 4; i++) {
            const int idx = i * 256 + tid;          // 0..1023
            const int r = idx >> 3, c = idx & 7;
            const uint32_t off = r * ROWB + c * 16;
            CP_ASYNC16(sb + OFF_A + off, &ag[(size_t)(bBase + r) * 8 + c]);
            CP_ASYNC16(sb + OFF_B + off, &bg[(size_t)(dBase + r) * 8 + c]);
        }
        CP_COMMIT();
        CP_WAIT0();
    }
    __syncthreads();

    const int wm = wid & 3;           // m warp (0..3)
    const int wn = wid >> 2;          // n warp (0..1)

    // ldmatrix lane address components
    const int lr = lane & 7;
    const int seg = lane >> 3;        // 0..3
    const int row_off = (seg & 1) * 8 + lr;
    const int k_off = (seg >> 1) * 8;

    float acc[2][8][4];
#pragma unroll
    for (int mt = 0; mt < 2; mt++)
#pragma unroll
        for (int nt = 0; nt < 8; nt++)
#pragma unroll
            for (int q = 0; q < 4; q++) acc[mt][nt][q] = 0.f;

#pragma unroll
    for (int ks = 0; ks < 4; ks++) {
        const int kb = (ks * 16 + k_off) * 2;       // byte offset along k

        uint32_t ah[2][4];
#pragma unroll
        for (int mt = 0; mt < 2; mt++) {
            const int m = wm * 32 + mt * 16 + row_off;
            LDSM_X4(ah[mt][0], ah[mt][1], ah[mt][2], ah[mt][3], sb + OFF_A + m * ROWB + kb);
        }

#pragma unroll
        for (int p = 0; p < 4; p++) {               // covers nt = 2p, 2p+1
            const int n = wn * 64 + p * 16 + row_off;
            uint32_t b0, b1, b2, b3;
            LDSM_X4(b0, b1, b2, b3, sb + OFF_B + n * ROWB + kb);
            MMA16816(acc[0][2*p],   ah[0], b0, b2);
            MMA16816(acc[1][2*p],   ah[1], b0, b2);
            MMA16816(acc[0][2*p+1], ah[0], b1, b3);
            MMA16816(acc[1][2*p+1], ah[1], b1, b3);
        }
    }

    // --- epilogue: direct float2 stores ---
#pragma unroll
    for (int mt = 0; mt < 2; mt++) {
        const int m = bBase + wm * 32 + mt * 16 + g;
#pragma unroll
        for (int nt = 0; nt < 8; nt++) {
            const int col = dBase + wn * 64 + nt * 8 + t * 2;
            *(float2*)&out[(size_t)m * EMB_DIM + col] =
                make_float2(acc[mt][nt][0], acc[mt][nt][1]);
            *(float2*)&out[(size_t)(m + 8) * EMB_DIM + col] =
                make_float2(acc[mt][nt][2], acc[mt][nt][3]);
        }
    }
}

// ---------------------------------------------------------------------------
// Launch
// ---------------------------------------------------------------------------
extern "C" void kernel_launch(void* const* d_in, const int* in_sizes, int n_in,
                              void* d_out, int out_size) {
    const int* ids = nullptr;
    const float* ratio = nullptr;
    const float* emb = nullptr;
    for (int i = 0; i < n_in; i++) {
        if (in_sizes[i] == N_COMP * SEQ_L)      ids   = (const int*)d_in[i];
        else if (in_sizes[i] == BATCH * N_COMP) ratio = (const float*)d_in[i];
        else                                     emb   = (const float*)d_in[i];
    }
    float* out = (float*)d_out;

    {   // pool partials (proven simple loop)
        dim3 grid(N_COMP, 4, SPLIT);            // 2048 blocks
        pool_kernel<<<grid, 128>>>(ids, emb);
    }
    {   // pooled reduce/round/transpose + ratio fp16
        cvt_kernel<<<192, 128>>>(ratio);
    }
    {   // HMMA mix (fp16 single product, cp.async staging)
        static bool attr_set = false;
        if (!attr_set) {
            cudaFuncSetAttribute(mix_kernel,
                                 cudaFuncAttributeMaxDynamicSharedMemorySize,
                                 MIX_SMEM);
            attr_set = true;
        }
        dim3 grid(EMB_DIM / 128, BATCH / 128);  // (16, 32)
        mix_kernel<<<grid, 256, MIX_SMEM>>>(out);
    }
}

// round 14
// speedup vs baseline: 1.0106x; 1.0106x over previous
#include <cuda_runtime.h>
#include <cuda_fp16.h>
#include <cstdint>

#define VOCAB   32000
#define EMB_DIM 2048
#define N_COMP  64
#define SEQ_L   128
#define BATCH   4096
#define SPLIT   8

// ---------------------------------------------------------------------------
// Static scratch (no allocation)
// ---------------------------------------------------------------------------
__device__ float  g_part[SPLIT][N_COMP * EMB_DIM];   // pool partials (4 MB)
__device__ __half g_BT[EMB_DIM * N_COMP];            // pooled^T fp16 [n][k]
__device__ __half g_A[BATCH * N_COMP];               // ratio fp16 [b][k]

// ---------------------------------------------------------------------------
// Kernel 1: pooled partial sums, FULL-ROW blocks.
// grid=(N_COMP, SPLIT), block=512. Each block: 16 tokens x full 8KB row.
// Thread t owns float4 column t -> every token row is one contiguous
// 8KB burst issued by co-scheduled warps of one block.
// ---------------------------------------------------------------------------
__global__ void __launch_bounds__(512)
pool_kernel(const int* __restrict__ ids, const float* __restrict__ emb) {
    __shared__ int s_ids[SEQ_L / SPLIT];
    const int comp = blockIdx.x;
    const int z = blockIdx.y;
    const int t = threadIdx.x;                  // 0..511 = float4 column
    const int TOK = SEQ_L / SPLIT;              // 16
    if (t < TOK) s_ids[t] = ids[comp * SEQ_L + z * TOK + t];
    __syncthreads();

    const float4* __restrict__ emb4 = (const float4*)emb;

    float4 acc = make_float4(0.f, 0.f, 0.f, 0.f);
#pragma unroll
    for (int l = 0; l < TOK; l++) {
        const int row = s_ids[l];
        float4 v = __ldg(&emb4[(size_t)row * (EMB_DIM / 4) + t]);
        acc.x += v.x; acc.y += v.y; acc.z += v.z; acc.w += v.w;
    }
    ((float4*)g_part[z])[comp * (EMB_DIM / 4) + t] = acc;
}

// ---------------------------------------------------------------------------
// fp16 helpers
// ---------------------------------------------------------------------------
__device__ __forceinline__ uint32_t pack_h2(__half a, __half b) {
    __half2 h = __halves2half2(a, b);
    return *reinterpret_cast<uint32_t*>(&h);
}

// ---------------------------------------------------------------------------
// Kernel 2: converts. blocks 0..63: pooled reduce+scale+round+transpose.
//           blocks 64..191: ratio fp32 -> fp16 (coalesced).
// ---------------------------------------------------------------------------
__global__ void cvt_kernel(const float* __restrict__ ratio) {
    const int bx = blockIdx.x;
    if (bx < 64) {
        const int lane = threadIdx.x & 31;
        const int ty = threadIdx.x >> 5;            // 0..3
        const int n = bx * 32 + lane;               // 0..2047
        const int k0 = ty * 16;

        uint32_t h2[8];
#pragma unroll
        for (int kp = 0; kp < 8; kp++) {
            float sa = 0.f, sb = 0.f;
#pragma unroll
            for (int z = 0; z < SPLIT; z++) {
                sa += g_part[z][(k0 + 2 * kp) * EMB_DIM + n];
                sb += g_part[z][(k0 + 2 * kp + 1) * EMB_DIM + n];
            }
            h2[kp] = pack_h2(__float2half_rn(sa * (1.0f / SEQ_L)),
                             __float2half_rn(sb * (1.0f / SEQ_L)));
        }
        uint4* dh = (uint4*)g_BT;      // row n = 8 uint4 (64 fp16)
#pragma unroll
        for (int c = 0; c < 2; c++) {
            dh[n * 8 + ty * 2 + c] = make_uint4(h2[4*c], h2[4*c+1], h2[4*c+2], h2[4*c+3]);
        }
    } else {
        const int base = (bx - 64) * 512;           // float4 index base
        const float4* __restrict__ rg = (const float4*)ratio;
        uint2* __restrict__ dst = (uint2*)g_A;
#pragma unroll
        for (int j = 0; j < 4; j++) {
            const int gid = base + j * 128 + threadIdx.x;  // 0..65535
            float4 v = __ldg(&rg[gid]);
            dst[gid] = make_uint2(pack_h2(__float2half_rn(v.x), __float2half_rn(v.y)),
                                  pack_h2(__float2half_rn(v.z), __float2half_rn(v.w)));
        }
    }
}

// ---------------------------------------------------------------------------
// Kernel 3: HMMA mix, single fp16 product, cp.async staging (unchanged).
// CTA: 128 b-rows x 128 d-cols, 256 threads (4 warps m x 2 warps n).
// ---------------------------------------------------------------------------
#define MMA16816(c, a, b0, b1) \
    asm volatile("mma.sync.aligned.m16n8k16.row.col.f32.f16.f16.f32 " \
        "{%0,%1,%2,%3}, {%4,%5,%6,%7}, {%8,%9}, {%0,%1,%2,%3};" \
        : "+f"((c)[0]), "+f"((c)[1]), "+f"((c)[2]), "+f"((c)[3]) \
        : "r"((a)[0]), "r"((a)[1]), "r"((a)[2]), "r"((a)[3]), "r"(b0), "r"(b1))

#define LDSM_X4(r0, r1, r2, r3, addr) \
    asm volatile("ldmatrix.sync.aligned.m8n8.x4.shared.b16 {%0,%1,%2,%3}, [%4];" \
        : "=r"(r0), "=r"(r1), "=r"(r2), "=r"(r3) : "r"(addr))

#define CP_ASYNC16(dst, src) \
    asm volatile("cp.async.ca.shared.global [%0], [%1], 16;" :: "r"(dst), "l"(src))
#define CP_COMMIT() asm volatile("cp.async.commit_group;" ::: "memory")
#define CP_WAIT0()  asm volatile("cp.async.wait_group 0;" ::: "memory")

#define ROWB 144            // padded row pitch in bytes (72 halves)
#define OFF_A  0
#define OFF_B  (128 * ROWB)
#define MIX_SMEM (2 * 128 * ROWB)   // 36864 B

__device__ __forceinline__ uint32_t smem_u32(const void* p) {
    uint32_t a;
    asm("{ .reg .u64 t; cvta.to.shared.u64 t, %1; cvt.u32.u64 %0, t; }" : "=r"(a) : "l"(p));
    return a;
}

__global__ void __launch_bounds__(256)
mix_kernel(float* __restrict__ out) {
    extern __shared__ char smem[];
    const uint32_t sb = smem_u32(smem);

    const int tid = threadIdx.x;
    const int wid = tid >> 5;
    const int lane = tid & 31;
    const int g = lane >> 2;          // 0..7
    const int t = lane & 3;           // 0..3
    const int dBase = blockIdx.x * 128;
    const int bBase = blockIdx.y * 128;

    // --- stage A + B via cp.async: both are 128 rows x 8 int4 (128 B) ---
    {
        const int4* __restrict__ ag = (const int4*)g_A;
        const int4* __restrict__ bg = (const int4*)g_BT;
#pragma unroll
        for (int i = 0; i < 4; i++) {
            const int idx = i * 256 + tid;          // 0..1023
            const int r = idx >> 3, c = idx & 7;
            const uint32_t off = r * ROWB + c * 16;
            CP_ASYNC16(sb + OFF_A + off, &ag[(size_t)(bBase + r) * 8 + c]);
            CP_ASYNC16(sb + OFF_B + off, &bg[(size_t)(dBase + r) * 8 + c]);
        }
        CP_COMMIT();
        CP_WAIT0();
    }
    __syncthreads();

    const int wm = wid & 3;           // m warp (0..3)
    const int wn = wid >> 2;          // n warp (0..1)

    // ldmatrix lane address components
    const int lr = lane & 7;
    const int seg = lane >> 3;        // 0..3
    const int row_off = (seg & 1) * 8 + lr;
    const int k_off = (seg >> 1) * 8;

    float acc[2][8][4];
#pragma unroll
    for (int mt = 0; mt < 2; mt++)
#pragma unroll
        for (int nt = 0; nt < 8; nt++)
#pragma unroll
            for (int q = 0; q < 4; q++) acc[mt][nt][q] = 0.f;

#pragma unroll
    for (int ks = 0; ks < 4; ks++) {
        const int kb = (ks * 16 + k_off) * 2;       // byte offset along k

        uint32_t ah[2][4];
#pragma unroll
        for (int mt = 0; mt < 2; mt++) {
            const int m = wm * 32 + mt * 16 + row_off;
            LDSM_X4(ah[mt][0], ah[mt][1], ah[mt][2], ah[mt][3], sb + OFF_A + m * ROWB + kb);
        }

#pragma unroll
        for (int p = 0; p < 4; p++) {               // covers nt = 2p, 2p+1
            const int n = wn * 64 + p * 16 + row_off;
            uint32_t b0, b1, b2, b3;
            LDSM_X4(b0, b1, b2, b3, sb + OFF_B + n * ROWB + kb);
            MMA16816(acc[0][2*p],   ah[0], b0, b2);
            MMA16816(acc[1][2*p],   ah[1], b0, b2);
            MMA16816(acc[0][2*p+1], ah[0], b1, b3);
            MMA16816(acc[1][2*p+1], ah[1], b1, b3);
        }
    }

    // --- epilogue: direct float2 stores ---
#pragma unroll
    for (int mt = 0; mt < 2; mt++) {
        const int m = bBase + wm * 32 + mt * 16 + g;
#pragma unroll
        for (int nt = 0; nt < 8; nt++) {
            const int col = dBase + wn * 64 + nt * 8 + t * 2;
            *(float2*)&out[(size_t)m * EMB_DIM + col] =
                make_float2(acc[mt][nt][0], acc[mt][nt][1]);
            *(float2*)&out[(size_t)(m + 8) * EMB_DIM + col] =
                make_float2(acc[mt][nt][2], acc[mt][nt][3]);
        }
    }
}

// ---------------------------------------------------------------------------
// Launch
// ---------------------------------------------------------------------------
extern "C" void kernel_launch(void* const* d_in, const int* in_sizes, int n_in,
                              void* d_out, int out_size) {
    const int* ids = nullptr;
    const float* ratio = nullptr;
    const float* emb = nullptr;
    for (int i = 0; i < n_in; i++) {
        if (in_sizes[i] == N_COMP * SEQ_L)      ids   = (const int*)d_in[i];
        else if (in_sizes[i] == BATCH * N_COMP) ratio = (const float*)d_in[i];
        else                                     emb   = (const float*)d_in[i];
    }
    float* out = (float*)d_out;

    {   // pool partials (full-row burst blocks)
        dim3 grid(N_COMP, SPLIT);               // 512 blocks x 512 threads
        pool_kernel<<<grid, 512>>>(ids, emb);
    }
    {   // pooled reduce/round/transpose + ratio fp16
        cvt_kernel<<<192, 128>>>(ratio);
    }
    {   // HMMA mix (fp16 single product, cp.async staging)
        static bool attr_set = false;
        if (!attr_set) {
            cudaFuncSetAttribute(mix_kernel,
                                 cudaFuncAttributeMaxDynamicSharedMemorySize,
                                 MIX_SMEM);
            attr_set = true;
        }
        dim3 grid(EMB_DIM / 128, BATCH / 128);  // (16, 32)
        mix_kernel<<<grid, 256, MIX_SMEM>>>(out);
    }
}